// round 12
// baseline (speedup 1.0000x reference)
#include <cuda_runtime.h>
#include <cstdint>
#include <math.h>

#define BB 8
#define NN 4096
#define KK 16

typedef unsigned long long ull;
#define FMA2(d,a,b) asm("fma.rn.f32x2 %0, %1, %2, %0;" : "+l"(d) : "l"(a), "l"(b))

__device__ int    g_idx[BB*NN*KK];
__device__ float  g_kd[2*BB*NN*KK];
__device__ int    g_ki[2*BB*NN*KK];
__device__ float  g_G[BB*NN*64];
__device__ float  g_H[BB*NN*64];
__device__ float  g_y1[(size_t)BB*NN*KK*64];
__device__ float  g_mx[(size_t)BB*NN*128];
__device__ float  g_mn[(size_t)BB*NN*128];
__device__ double g_sum0[64], g_sq0[64], g_sum1[64], g_sq1[64], g_sum2[128], g_sq2[128];

__device__ __forceinline__ int swi(int col, int c) {
    return (col << 6) + ((((c >> 2) ^ col) & 15) << 2) + (c & 3);
}
__device__ __forceinline__ int swi4(int col, int chunk) {
    return (col << 6) + (((chunk ^ col) & 15) << 2);
}
__device__ __forceinline__ float lo32(ull u) { return __uint_as_float((unsigned)u); }
__device__ __forceinline__ float hi32(ull u) { return __uint_as_float((unsigned)(u >> 32)); }
__device__ __forceinline__ unsigned int shaddr(const void* p) {
    return (unsigned int)__cvta_generic_to_shared(p);
}
__device__ __forceinline__ void cp_async16(unsigned int s, const void* g) {
    asm volatile("cp.async.cg.shared.global [%0], [%1], 16;" :: "r"(s), "l"(g) : "memory");
}
__device__ __forceinline__ void cp_commit() {
    asm volatile("cp.async.commit_group;" ::: "memory");
}
__device__ __forceinline__ void cp_wait0() {
    asm volatile("cp.async.wait_group 0;" ::: "memory");
}

// ---------------- KNN over a 2048-ref chunk; block(0,0,0) zeroes stat accumulators ----------------
__global__ __launch_bounds__(128) void knn_part_kernel(const float* __restrict__ q,
                                                       const float* __restrict__ r) {
    if (blockIdx.x == 0 && blockIdx.y == 0 && blockIdx.z == 0) {
        int i = threadIdx.x;
        if (i < 64) { g_sum0[i]=0.0; g_sq0[i]=0.0; g_sum1[i]=0.0; g_sq1[i]=0.0; }
        if (i < 128){ g_sum2[i]=0.0; g_sq2[i]=0.0; }
    }
    __shared__ float4 refs[512];
    int chunk = blockIdx.z;
    int b = blockIdx.y;
    int n = blockIdx.x * 128 + threadIdx.x;
    const float* qb = q + b*3*NN;
    float qx = qb[n], qy = qb[NN+n], qz = qb[2*NN+n];
    float q2 = qx*qx + qy*qy + qz*qz;
    float dist[16]; int ind[16];
#pragma unroll
    for (int i = 0; i < 16; i++) { dist[i] = 3.4e38f; ind[i] = 0; }
    const float* rb = r + b*3*NN;
    int t0 = chunk * 2048;
    for (int t = t0; t < t0 + 2048; t += 512) {
        __syncthreads();
        for (int j = threadIdx.x; j < 512; j += 128) {
            float rx = rb[t+j], ry = rb[NN+t+j], rz = rb[2*NN+t+j];
            refs[j] = make_float4(rx, ry, rz, rx*rx + ry*ry + rz*rz);
        }
        __syncthreads();
#pragma unroll 2
        for (int j = 0; j < 512; j++) {
            float4 rv = refs[j];
            float dot = fmaf(qx, rv.x, fmaf(qy, rv.y, qz*rv.z));
            float d = fmaf(-2.f, dot, q2 + rv.w);
            if (d < dist[15]) {
                float dd = d; int mi = t + j;
#pragma unroll
                for (int s = 0; s < 16; s++) {
                    if (dd < dist[s]) {
                        float td = dist[s]; dist[s] = dd; dd = td;
                        int   ti = ind[s];  ind[s]  = mi; mi = ti;
                    }
                }
            }
        }
    }
    int base = ((b*NN + n)*2 + chunk)*16;
#pragma unroll
    for (int i = 0; i < 16; i++) { g_kd[base+i] = dist[i]; g_ki[base+i] = ind[i]; }
}

__global__ void knn_merge_kernel() {
    int bn = blockIdx.x * 256 + threadIdx.x;
    float da[32]; int ia[32];
    const float* dp = g_kd + (size_t)bn*32;
    const int*   ip = g_ki + (size_t)bn*32;
#pragma unroll
    for (int i = 0; i < 32; i++) { da[i] = dp[i]; ia[i] = ip[i]; }
    int a = 0, c = 16;
    int base = bn*16;
#pragma unroll
    for (int o = 0; o < 16; o++) {
        bool takeA = da[a] <= da[c];
        g_idx[base+o] = takeA ? ia[a] : ia[c];
        a += takeA; c += !takeA;
    }
}

// ---------------- G/H GEMM (512 blocks; side stream, concurrent with KNN) ----------------
__global__ __launch_bounds__(256) void gh_kernel(const float* __restrict__ pos1,
                                                 const float* __restrict__ pos2,
                                                 const float* __restrict__ f1,
                                                 const float* __restrict__ f2,
                                                 const float* __restrict__ W0) {
    __shared__ float Wt[67][32];
    __shared__ float Xs[8][256];
    int tid = threadIdx.x;
    int g = blockIdx.x;
    int isH = g >> 8;
    int oh  = (g >> 7) & 1;
    int bt  = g & 127;
    int b = bt >> 4, m0 = (bt & 15) * 256;
    const float* pos  = isH ? pos1 : pos2;
    const float* feat = isH ? f1   : f2;
    for (int i = tid; i < 32*67; i += 256) {
        int o = i & 31, c = i >> 5;
        int gc = (c < 3) ? c : (isH ? c + 64 : c);
        Wt[c][o] = W0[(oh*32 + o)*131 + gc];
    }
    __syncthreads();
    int m = m0 + tid;
    const float* pp = pos + b*3*NN;
    float p0 = pp[m], p1 = pp[NN+m], p2 = pp[2*NN+m];
    if (isH) { p0 = -p0; p1 = -p1; p2 = -p2; }
    float acc[32];
#pragma unroll
    for (int o = 0; o < 32; o++)
        acc[o] = fmaf(Wt[0][o], p0, fmaf(Wt[1][o], p1, Wt[2][o]*p2));
    const float* fb = feat + (size_t)b*64*NN + m0;
    for (int cc = 0; cc < 64; cc += 8) {
        __syncthreads();
        for (int i = tid; i < 2048; i += 256) {
            int r = i >> 8, mm = i & 255;
            Xs[r][mm] = fb[(size_t)(cc + r)*NN + mm];
        }
        __syncthreads();
#pragma unroll
        for (int r = 0; r < 8; r++) {
            float x = Xs[r][tid];
            const float* w = &Wt[3 + cc + r][0];
#pragma unroll
            for (int o4 = 0; o4 < 32; o4 += 4) {
                float4 wv = *(const float4*)(w + o4);
                acc[o4+0] = fmaf(wv.x, x, acc[o4+0]);
                acc[o4+1] = fmaf(wv.y, x, acc[o4+1]);
                acc[o4+2] = fmaf(wv.z, x, acc[o4+2]);
                acc[o4+3] = fmaf(wv.w, x, acc[o4+3]);
            }
        }
    }
    float* outp = (isH ? g_H : g_G) + ((size_t)((b<<12) + m) << 6) + oh*32;
#pragma unroll
    for (int o4 = 0; o4 < 32; o4 += 4)
        *(float4*)(outp + o4) = make_float4(acc[o4], acc[o4+1], acc[o4+2], acc[o4+3]);
}

__global__ void stats0_kernel() {
    __shared__ float bsum[64], bsq[64];
    int tid = threadIdx.x;
    if (tid < 64) { bsum[tid] = 0.f; bsq[tid] = 0.f; }
    __syncthreads();
    int warp = tid >> 5, lane = tid & 31;
    int c4 = lane & 15, r2 = lane >> 4;
    int p0 = blockIdx.x*16 + warp*2;
    int p1 = p0 + 1;
    int b = p0 >> 12;
    int mk = g_idx[p0*16 + lane];
    float4 hA = *(const float4*)(g_H + (size_t)p0*64 + c4*4);
    float4 hB = *(const float4*)(g_H + (size_t)p1*64 + c4*4);
    float4 s = make_float4(0,0,0,0), qq = make_float4(0,0,0,0);
#pragma unroll
    for (int st = 0; st < 16; st++) {
        int row = 2*st + r2;
        int m = __shfl_sync(0xffffffffu, mk, row);
        float4 g4 = *(const float4*)(g_G + ((size_t)((b<<12) + m) << 6) + (c4<<2));
        float4 h = (row < 16) ? hA : hB;
        float vx = g4.x + h.x, vy = g4.y + h.y, vz = g4.z + h.z, vw = g4.w + h.w;
        s.x += vx; s.y += vy; s.z += vz; s.w += vw;
        qq.x = fmaf(vx, vx, qq.x); qq.y = fmaf(vy, vy, qq.y);
        qq.z = fmaf(vz, vz, qq.z); qq.w = fmaf(vw, vw, qq.w);
    }
    s.x += __shfl_xor_sync(0xffffffffu, s.x, 16);
    s.y += __shfl_xor_sync(0xffffffffu, s.y, 16);
    s.z += __shfl_xor_sync(0xffffffffu, s.z, 16);
    s.w += __shfl_xor_sync(0xffffffffu, s.w, 16);
    qq.x += __shfl_xor_sync(0xffffffffu, qq.x, 16);
    qq.y += __shfl_xor_sync(0xffffffffu, qq.y, 16);
    qq.z += __shfl_xor_sync(0xffffffffu, qq.z, 16);
    qq.w += __shfl_xor_sync(0xffffffffu, qq.w, 16);
    if (lane < 16) {
        atomicAdd(&bsum[c4*4+0], s.x); atomicAdd(&bsum[c4*4+1], s.y);
        atomicAdd(&bsum[c4*4+2], s.z); atomicAdd(&bsum[c4*4+3], s.w);
        atomicAdd(&bsq[c4*4+0], qq.x); atomicAdd(&bsq[c4*4+1], qq.y);
        atomicAdd(&bsq[c4*4+2], qq.z); atomicAdd(&bsq[c4*4+3], qq.w);
    }
    __syncthreads();
    if (tid < 64) { atomicAdd(&g_sum0[tid], (double)bsum[tid]); atomicAdd(&g_sq0[tid], (double)bsq[tid]); }
}

// ---------------- layer1: persistent, cp.async double-buffered ----------------
__global__ __launch_bounds__(256,2) void layer1_kernel(const float* __restrict__ W1,
                                                       const float* __restrict__ gg0,
                                                       const float* __restrict__ bb0) {
    extern __shared__ float sm[];
    float* Ws   = sm;                    // 4096
    float* xs   = sm + 4096;             // 2*8192
    float* hs   = sm + 4096 + 16384;     // 2*512
    float* s0s  = hs + 1024;             // 64
    float* t0s  = s0s + 64;              // 64
    float* bsum = t0s + 64;              // 64
    float* bsq  = bsum + 64;             // 64
    int*   idxb = (int*)(bsq + 64);      // 2*128
    int tid = threadIdx.x;
    for (int i = tid; i < 4096; i += 256) { int o=i>>6, c=i&63; Ws[swi(o,c)] = W1[i]; }
    if (tid < 64) {
        const double cnt = (double)BB*NN*KK;
        double mean = g_sum0[tid] / cnt;
        double var  = g_sq0[tid] / cnt - mean*mean;
        float sv = gg0[tid] * rsqrtf((float)var + 1e-5f);
        s0s[tid] = sv;
        t0s[tid] = bb0[tid] - (float)mean * sv;
        bsum[tid] = 0.f; bsq[tid] = 0.f;
    }
    int GRID = gridDim.x;
    int T0 = blockIdx.x;
    if (tid < 128) {
        idxb[tid] = g_idx[T0*128 + tid];
        if (T0 + GRID < 4096) idxb[128 + tid] = g_idx[(T0+GRID)*128 + tid];
        cp_async16(shaddr(hs + tid*4), g_H + (size_t)T0*512 + tid*4);
    }
    __syncthreads();
    {
        int bb = T0 >> 9;
#pragma unroll
        for (int k = 0; k < 8; k++) {
            int i = tid + k*256, col = i>>4, c4 = i&15;
            int m = idxb[col];
            cp_async16(shaddr(xs + swi4(col,c4)),
                       g_G + (((size_t)(bb<<12) + m)<<6) + (c4<<2));
        }
    }
    cp_commit();
    int p = 0, t = 0;
    for (int T = T0; T < 4096; T += GRID, t++) {
        int pbase = T*8;
        float* xsp = xs + p*8192;
        float* hsp = hs + p*512;
        cp_wait0(); __syncthreads();
        const float4* s0v = (const float4*)s0s;
        const float4* t0v = (const float4*)t0s;
#pragma unroll
        for (int k = 0; k < 8; k++) {
            int i = tid + k*256, col = i>>4, c4 = i&15;
            float4 g4 = *(float4*)(xsp + swi4(col,c4));
            float4 h4 = *(float4*)(hsp + (col>>4)*64 + (c4<<2));
            float4 sv = s0v[c4], tv = t0v[c4], v;
            v.x = fmaxf(fmaf(sv.x, g4.x+h4.x, tv.x), 0.f);
            v.y = fmaxf(fmaf(sv.y, g4.y+h4.y, tv.y), 0.f);
            v.z = fmaxf(fmaf(sv.z, g4.z+h4.z, tv.z), 0.f);
            v.w = fmaxf(fmaf(sv.w, g4.w+h4.w, tv.w), 0.f);
            *(float4*)(xsp + swi4(col,c4)) = v;
        }
        __syncthreads();
        int Tn = T + GRID;
        int nreg = 0;
        bool hasN2 = false;
        if (Tn < 4096) {
            float* xsn = xs + (p^1)*8192;
            const int* ib = idxb + ((t+1)&1)*128;
            int bb = Tn >> 9;
#pragma unroll
            for (int k = 0; k < 8; k++) {
                int i = tid + k*256, col = i>>4, c4 = i&15;
                int m = ib[col];
                cp_async16(shaddr(xsn + swi4(col,c4)),
                           g_G + (((size_t)(bb<<12) + m)<<6) + (c4<<2));
            }
            if (tid < 128) cp_async16(shaddr(hs + (p^1)*512 + tid*4),
                                      g_H + (size_t)Tn*512 + tid*4);
            cp_commit();
            int T2 = T + 2*GRID;
            if (tid < 128 && T2 < 4096) { nreg = g_idx[T2*128 + tid]; hasN2 = true; }
        }
        int ty = tid >> 5, tx = tid & 31;
        int o0 = ty * 8;
        ull acc2[8][4];
#pragma unroll
        for (int i = 0; i < 8; i++)
#pragma unroll
            for (int j = 0; j < 4; j++) acc2[i][j] = 0ull;
#pragma unroll
        for (int c4 = 0; c4 < 16; c4++) {
            ulonglong2 xv[4];
#pragma unroll
            for (int j = 0; j < 4; j++) xv[j] = *(const ulonglong2*)(xsp + swi4(tx + 32*j, c4));
#pragma unroll
            for (int ih = 0; ih < 2; ih++) {
                ulonglong2 wv[4];
#pragma unroll
                for (int i = 0; i < 4; i++) wv[i] = *(const ulonglong2*)(Ws + swi4(o0 + ih*4 + i, c4));
#pragma unroll
                for (int i = 0; i < 4; i++)
#pragma unroll
                    for (int j = 0; j < 4; j++) {
                        FMA2(acc2[ih*4+i][j], wv[i].x, xv[j].x);
                        FMA2(acc2[ih*4+i][j], wv[i].y, xv[j].y);
                    }
            }
        }
        float v[8][4];
#pragma unroll
        for (int i = 0; i < 8; i++)
#pragma unroll
            for (int j = 0; j < 4; j++) v[i][j] = lo32(acc2[i][j]) + hi32(acc2[i][j]);
#pragma unroll
        for (int j = 0; j < 4; j++) {
            int col = tx + 32*j;
            float* yp = g_y1 + (((size_t)(pbase + (col>>4))*16 + (col&15))<<6) + o0;
            *(float4*)yp       = make_float4(v[0][j], v[1][j], v[2][j], v[3][j]);
            *(float4*)(yp + 4) = make_float4(v[4][j], v[5][j], v[6][j], v[7][j]);
        }
#pragma unroll
        for (int i = 0; i < 8; i++) {
            float ps = 0.f, pq = 0.f;
#pragma unroll
            for (int j = 0; j < 4; j++) { ps += v[i][j]; pq = fmaf(v[i][j], v[i][j], pq); }
#pragma unroll
            for (int s = 16; s >= 1; s >>= 1) {
                ps += __shfl_xor_sync(0xffffffffu, ps, s);
                pq += __shfl_xor_sync(0xffffffffu, pq, s);
            }
            if (tx == 0) { bsum[o0+i] += ps; bsq[o0+i] += pq; }
        }
        if (hasN2) idxb[(t&1)*128 + tid] = nreg;
        __syncthreads();
        p ^= 1;
    }
    if (tid < 64) { atomicAdd(&g_sum1[tid], (double)bsum[tid]); atomicAdd(&g_sq1[tid], (double)bsq[tid]); }
}

// ---------------- layer2: persistent, cp.async double-buffered ----------------
__global__ __launch_bounds__(512,1) void layer2_kernel(const float* __restrict__ W2,
                                                       const float* __restrict__ gg1,
                                                       const float* __restrict__ bb1) {
    extern __shared__ float sm[];
    float* Ws   = sm;                  // 8192
    float* xs   = sm + 8192;           // 2*8192
    float* s1s  = sm + 8192 + 16384;   // 64
    float* t1s  = s1s + 64;            // 64
    float* bsum = t1s + 64;            // 128
    float* bsq  = bsum + 128;          // 128
    int tid = threadIdx.x;
    for (int i = tid; i < 8192; i += 512) { int o=i>>6, c=i&63; Ws[swi(o,c)] = W2[i]; }
    if (tid < 64) {
        const double cnt = (double)BB*NN*KK;
        double mean = g_sum1[tid] / cnt;
        double var  = g_sq1[tid] / cnt - mean*mean;
        float sv = gg1[tid] * rsqrtf((float)var + 1e-5f);
        s1s[tid] = sv;
        t1s[tid] = bb1[tid] - (float)mean * sv;
    }
    if (tid < 128) { bsum[tid] = 0.f; bsq[tid] = 0.f; }
    int GRID = gridDim.x;
    int T0 = blockIdx.x;
#pragma unroll
    for (int k = 0; k < 4; k++) {
        int i = tid + k*512, col = i>>4, c4 = i&15;
        cp_async16(shaddr(xs + swi4(col,c4)), g_y1 + (size_t)T0*8192 + col*64 + (c4<<2));
    }
    cp_commit();
    int p = 0;
    for (int T = T0; T < 4096; T += GRID) {
        int pbase = T*8;
        float* xsp = xs + p*8192;
        cp_wait0(); __syncthreads();
        const float4* s1v = (const float4*)s1s;
        const float4* t1v = (const float4*)t1s;
#pragma unroll
        for (int k = 0; k < 4; k++) {
            int i = tid + k*512, col = i>>4, c4 = i&15;
            float4 y = *(float4*)(xsp + swi4(col,c4));
            float4 sv = s1v[c4], tv = t1v[c4], v;
            v.x = fmaxf(fmaf(sv.x, y.x, tv.x), 0.f);
            v.y = fmaxf(fmaf(sv.y, y.y, tv.y), 0.f);
            v.z = fmaxf(fmaf(sv.z, y.z, tv.z), 0.f);
            v.w = fmaxf(fmaf(sv.w, y.w, tv.w), 0.f);
            *(float4*)(xsp + swi4(col,c4)) = v;
        }
        __syncthreads();
        int Tn = T + GRID;
        if (Tn < 4096) {
            float* xsn = xs + (p^1)*8192;
#pragma unroll
            for (int k = 0; k < 4; k++) {
                int i = tid + k*512, col = i>>4, c4 = i&15;
                cp_async16(shaddr(xsn + swi4(col,c4)),
                           g_y1 + (size_t)Tn*8192 + col*64 + (c4<<2));
            }
            cp_commit();
        }
        int ty = tid >> 5, tx = tid & 31;
        int o0 = ty * 8;
        ull acc2[8][4];
#pragma unroll
        for (int i = 0; i < 8; i++)
#pragma unroll
            for (int j = 0; j < 4; j++) acc2[i][j] = 0ull;
#pragma unroll
        for (int c4 = 0; c4 < 16; c4++) {
            ulonglong2 xv[4];
#pragma unroll
            for (int j = 0; j < 4; j++) xv[j] = *(const ulonglong2*)(xsp + swi4(tx + 32*j, c4));
#pragma unroll
            for (int ih = 0; ih < 2; ih++) {
                ulonglong2 wv[4];
#pragma unroll
                for (int i = 0; i < 4; i++) wv[i] = *(const ulonglong2*)(Ws + swi4(o0 + ih*4 + i, c4));
#pragma unroll
                for (int i = 0; i < 4; i++)
#pragma unroll
                    for (int j = 0; j < 4; j++) {
                        FMA2(acc2[ih*4+i][j], wv[i].x, xv[j].x);
                        FMA2(acc2[ih*4+i][j], wv[i].y, xv[j].y);
                    }
            }
        }
        float v[8][4];
#pragma unroll
        for (int i = 0; i < 8; i++)
#pragma unroll
            for (int j = 0; j < 4; j++) v[i][j] = lo32(acc2[i][j]) + hi32(acc2[i][j]);
#pragma unroll
        for (int i = 0; i < 8; i++) {
            float ps = 0.f, pq = 0.f;
#pragma unroll
            for (int j = 0; j < 4; j++) { ps += v[i][j]; pq = fmaf(v[i][j], v[i][j], pq); }
#pragma unroll
            for (int s = 16; s >= 1; s >>= 1) {
                ps += __shfl_xor_sync(0xffffffffu, ps, s);
                pq += __shfl_xor_sync(0xffffffffu, pq, s);
            }
            if (tx == 0) { bsum[o0+i] += ps; bsq[o0+i] += pq; }
        }
#pragma unroll
        for (int i = 0; i < 8; i++)
#pragma unroll
            for (int j = 0; j < 4; j++) {
                float mx = v[i][j], mn = v[i][j];
#pragma unroll
                for (int s = 8; s >= 1; s >>= 1) {
                    mx = fmaxf(mx, __shfl_xor_sync(0xffffffffu, mx, s, 16));
                    mn = fminf(mn, __shfl_xor_sync(0xffffffffu, mn, s, 16));
                }
                if ((tx & 15) == 0) {
                    int pp = 2*j + (tx >> 4);
                    g_mx[(size_t)(pbase + pp)*128 + o0 + i] = mx;
                    g_mn[(size_t)(pbase + pp)*128 + o0 + i] = mn;
                }
            }
        __syncthreads();
        p ^= 1;
    }
    if (tid < 128) { atomicAdd(&g_sum2[tid], (double)bsum[tid]); atomicAdd(&g_sq2[tid], (double)bsq[tid]); }
}

__global__ void final_out_kernel(float* __restrict__ out,
                                 const float* __restrict__ gg2,
                                 const float* __restrict__ bb2) {
    __shared__ float tile[32][129];
    __shared__ float s2s[128], t2s[128];
    int tid = threadIdx.x;
    if (tid < 128) {
        const double cnt = (double)BB*NN*KK;
        double mean = g_sum2[tid] / cnt;
        double var  = g_sq2[tid] / cnt - mean*mean;
        float sv = gg2[tid] * rsqrtf((float)var + 1e-5f);
        s2s[tid] = sv;
        t2s[tid] = bb2[tid] - (float)mean * sv;
    }
    __syncthreads();
    int bn0 = blockIdx.x * 32;
    int b = bn0 >> 12, n0 = bn0 & 4095;
    for (int i = tid; i < 32*128; i += 256) {
        int r = i >> 7, o = i & 127;
        float s = s2s[o], t = t2s[o];
        size_t p = (size_t)(bn0 + r)*128 + o;
        float v = fmaxf(fmaf(s, g_mx[p], t), fmaf(s, g_mn[p], t));
        tile[r][o] = fmaxf(v, 0.f);
    }
    __syncthreads();
    for (int i = tid; i < 4096; i += 256) {
        int o = i >> 5, j = i & 31;
        out[(size_t)b*128*NN + o*NN + n0 + j] = tile[j][o];
    }
}

extern "C" void kernel_launch(void* const* d_in, const int* in_sizes, int n_in,
                              void* d_out, int out_size) {
    const float* pos1   = (const float*)d_in[0];
    const float* pos1re = (const float*)d_in[1];
    const float* pos2   = (const float*)d_in[2];
    const float* f1     = (const float*)d_in[3];
    const float* f2     = (const float*)d_in[4];
    const float* W0 = (const float*)d_in[6];
    const float* g0 = (const float*)d_in[7];
    const float* b0 = (const float*)d_in[8];
    const float* W1 = (const float*)d_in[9];
    const float* g1 = (const float*)d_in[10];
    const float* b1 = (const float*)d_in[11];
    const float* W2 = (const float*)d_in[12];
    const float* g2 = (const float*)d_in[13];
    const float* b2 = (const float*)d_in[14];

    float* out = (float*)d_out;
    const size_t featElems = (size_t)BB*128*NN;
    const size_t posElems  = (size_t)BB*3*NN;
    float* featOut = out + ((size_t)out_size - featElems);
    if ((size_t)out_size > featElems)
        cudaMemcpyAsync(out, pos1, posElems*sizeof(float), cudaMemcpyDeviceToDevice);

    static bool inited = false;
    static cudaStream_t s2 = 0;
    static cudaEvent_t eF = 0, eJ = 0;
    if (!inited) {
        cudaFuncSetAttribute(layer1_kernel, cudaFuncAttributeMaxDynamicSharedMemorySize, 88064);
        cudaFuncSetAttribute(layer2_kernel, cudaFuncAttributeMaxDynamicSharedMemorySize, 99840);
        cudaStreamCreateWithFlags(&s2, cudaStreamNonBlocking);
        cudaEventCreateWithFlags(&eF, cudaEventDisableTiming);
        cudaEventCreateWithFlags(&eJ, cudaEventDisableTiming);
        inited = true;
    }

    // fork: gh on side stream, concurrent with KNN (no data dependency)
    cudaEventRecord(eF, 0);
    cudaStreamWaitEvent(s2, eF, 0);
    gh_kernel<<<512, 256, 0, s2>>>(pos1, pos2, f1, f2, W0);
    cudaEventRecord(eJ, s2);

    knn_part_kernel<<<dim3(32, 8, 2), 128>>>(pos1re, pos2);
    knn_merge_kernel<<<128, 256>>>();

    // join before stats0 (needs G/H + idx)
    cudaStreamWaitEvent(0, eJ, 0);
    stats0_kernel<<<2048, 256>>>();
    layer1_kernel<<<304, 256, 88064>>>(W1, g0, b0);
    layer2_kernel<<<152, 512, 99840>>>(W2, g1, b1);
    final_out_kernel<<<1024, 256>>>(featOut, g2, b2);
}

// round 13
// speedup vs baseline: 1.0779x; 1.0779x over previous
#include <cuda_runtime.h>
#include <cstdint>
#include <math.h>

#define BB 8
#define NN 4096
#define KK 16

typedef unsigned long long ull;
#define FMA2(d,a,b) asm("fma.rn.f32x2 %0, %1, %2, %0;" : "+l"(d) : "l"(a), "l"(b))

__device__ int    g_idx[BB*NN*KK];
__device__ float  g_kd[2*BB*NN*KK];
__device__ int    g_ki[2*BB*NN*KK];
__device__ float  g_G[BB*NN*64];
__device__ float  g_H[BB*NN*64];
__device__ float  g_y1[(size_t)BB*NN*KK*64];
__device__ float  g_mx[(size_t)BB*NN*128];
__device__ float  g_mn[(size_t)BB*NN*128];
__device__ double g_sum0[64], g_sq0[64], g_sum1[64], g_sq1[64], g_sum2[128], g_sq2[128];

__device__ __forceinline__ int swi(int col, int c) {
    return (col << 6) + ((((c >> 2) ^ col) & 15) << 2) + (c & 3);
}
__device__ __forceinline__ int swi4(int col, int chunk) {
    return (col << 6) + (((chunk ^ col) & 15) << 2);
}
__device__ __forceinline__ float lo32(ull u) { return __uint_as_float((unsigned)u); }
__device__ __forceinline__ float hi32(ull u) { return __uint_as_float((unsigned)(u >> 32)); }
__device__ __forceinline__ unsigned int shaddr(const void* p) {
    return (unsigned int)__cvta_generic_to_shared(p);
}
__device__ __forceinline__ void cp_async16(unsigned int s, const void* g) {
    asm volatile("cp.async.cg.shared.global [%0], [%1], 16;" :: "r"(s), "l"(g) : "memory");
}
__device__ __forceinline__ void cp_commit() {
    asm volatile("cp.async.commit_group;" ::: "memory");
}
__device__ __forceinline__ void cp_wait0() {
    asm volatile("cp.async.wait_group 0;" ::: "memory");
}

// ---------------- KNN over a 2048-ref chunk; block(0,0,0) zeroes stat accumulators ----------------
__global__ __launch_bounds__(128) void knn_part_kernel(const float* __restrict__ q,
                                                       const float* __restrict__ r) {
    if (blockIdx.x == 0 && blockIdx.y == 0 && blockIdx.z == 0) {
        int i = threadIdx.x;
        if (i < 64) { g_sum0[i]=0.0; g_sq0[i]=0.0; g_sum1[i]=0.0; g_sq1[i]=0.0; }
        if (i < 128){ g_sum2[i]=0.0; g_sq2[i]=0.0; }
    }
    __shared__ float4 refs[512];
    int chunk = blockIdx.z;
    int b = blockIdx.y;
    int n = blockIdx.x * 128 + threadIdx.x;
    const float* qb = q + b*3*NN;
    float qx = qb[n], qy = qb[NN+n], qz = qb[2*NN+n];
    float q2 = qx*qx + qy*qy + qz*qz;
    float dist[16]; int ind[16];
#pragma unroll
    for (int i = 0; i < 16; i++) { dist[i] = 3.4e38f; ind[i] = 0; }
    const float* rb = r + b*3*NN;
    int t0 = chunk * 2048;
    for (int t = t0; t < t0 + 2048; t += 512) {
        __syncthreads();
        for (int j = threadIdx.x; j < 512; j += 128) {
            float rx = rb[t+j], ry = rb[NN+t+j], rz = rb[2*NN+t+j];
            refs[j] = make_float4(rx, ry, rz, rx*rx + ry*ry + rz*rz);
        }
        __syncthreads();
#pragma unroll 2
        for (int j = 0; j < 512; j++) {
            float4 rv = refs[j];
            float dot = fmaf(qx, rv.x, fmaf(qy, rv.y, qz*rv.z));
            float d = fmaf(-2.f, dot, q2 + rv.w);
            if (d < dist[15]) {
                float dd = d; int mi = t + j;
#pragma unroll
                for (int s = 0; s < 16; s++) {
                    if (dd < dist[s]) {
                        float td = dist[s]; dist[s] = dd; dd = td;
                        int   ti = ind[s];  ind[s]  = mi; mi = ti;
                    }
                }
            }
        }
    }
    int base = ((b*NN + n)*2 + chunk)*16;
#pragma unroll
    for (int i = 0; i < 16; i++) { g_kd[base+i] = dist[i]; g_ki[base+i] = ind[i]; }
}

// ---------------- fused: blocks 0-127 = knn merge; blocks 128-639 = G/H GEMM ----------------
__global__ __launch_bounds__(256) void merge_gh_kernel(const float* __restrict__ pos1,
                                                       const float* __restrict__ pos2,
                                                       const float* __restrict__ f1,
                                                       const float* __restrict__ f2,
                                                       const float* __restrict__ W0) {
    __shared__ float Wt[67][32];
    __shared__ float Xs[8][256];
    int tid = threadIdx.x;
    if (blockIdx.x < 128) {
        int bn = blockIdx.x * 256 + tid;
        float da[32]; int ia[32];
        const float* dp = g_kd + (size_t)bn*32;
        const int*   ip = g_ki + (size_t)bn*32;
#pragma unroll
        for (int i = 0; i < 32; i++) { da[i] = dp[i]; ia[i] = ip[i]; }
        int a = 0, c = 16;
        int base = bn*16;
#pragma unroll
        for (int o = 0; o < 16; o++) {
            bool takeA = da[a] <= da[c];
            g_idx[base+o] = takeA ? ia[a] : ia[c];
            a += takeA; c += !takeA;
        }
        return;
    }
    int g = blockIdx.x - 128;
    int isH = g >> 8;
    int oh  = (g >> 7) & 1;
    int bt  = g & 127;
    int b = bt >> 4, m0 = (bt & 15) * 256;
    const float* pos  = isH ? pos1 : pos2;
    const float* feat = isH ? f1   : f2;
    for (int i = tid; i < 32*67; i += 256) {
        int o = i & 31, c = i >> 5;
        int gc = (c < 3) ? c : (isH ? c + 64 : c);
        Wt[c][o] = W0[(oh*32 + o)*131 + gc];
    }
    __syncthreads();
    int m = m0 + tid;
    const float* pp = pos + b*3*NN;
    float p0 = pp[m], p1 = pp[NN+m], p2 = pp[2*NN+m];
    if (isH) { p0 = -p0; p1 = -p1; p2 = -p2; }
    float acc[32];
#pragma unroll
    for (int o = 0; o < 32; o++)
        acc[o] = fmaf(Wt[0][o], p0, fmaf(Wt[1][o], p1, Wt[2][o]*p2));
    const float* fb = feat + (size_t)b*64*NN + m0;
    for (int cc = 0; cc < 64; cc += 8) {
        __syncthreads();
        for (int i = tid; i < 2048; i += 256) {
            int r = i >> 8, mm = i & 255;
            Xs[r][mm] = fb[(size_t)(cc + r)*NN + mm];
        }
        __syncthreads();
#pragma unroll
        for (int r = 0; r < 8; r++) {
            float x = Xs[r][tid];
            const float* w = &Wt[3 + cc + r][0];
#pragma unroll
            for (int o4 = 0; o4 < 32; o4 += 4) {
                float4 wv = *(const float4*)(w + o4);
                acc[o4+0] = fmaf(wv.x, x, acc[o4+0]);
                acc[o4+1] = fmaf(wv.y, x, acc[o4+1]);
                acc[o4+2] = fmaf(wv.z, x, acc[o4+2]);
                acc[o4+3] = fmaf(wv.w, x, acc[o4+3]);
            }
        }
    }
    float* outp = (isH ? g_H : g_G) + ((size_t)((b<<12) + m) << 6) + oh*32;
#pragma unroll
    for (int o4 = 0; o4 < 32; o4 += 4)
        *(float4*)(outp + o4) = make_float4(acc[o4], acc[o4+1], acc[o4+2], acc[o4+3]);
}

__global__ void stats0_kernel() {
    __shared__ float bsum[64], bsq[64];
    int tid = threadIdx.x;
    if (tid < 64) { bsum[tid] = 0.f; bsq[tid] = 0.f; }
    __syncthreads();
    int warp = tid >> 5, lane = tid & 31;
    int c4 = lane & 15, r2 = lane >> 4;
    int p0 = blockIdx.x*16 + warp*2;
    int p1 = p0 + 1;
    int b = p0 >> 12;
    int mk = g_idx[p0*16 + lane];
    float4 hA = *(const float4*)(g_H + (size_t)p0*64 + c4*4);
    float4 hB = *(const float4*)(g_H + (size_t)p1*64 + c4*4);
    float4 s = make_float4(0,0,0,0), qq = make_float4(0,0,0,0);
#pragma unroll
    for (int st = 0; st < 16; st++) {
        int row = 2*st + r2;
        int m = __shfl_sync(0xffffffffu, mk, row);
        float4 g4 = *(const float4*)(g_G + ((size_t)((b<<12) + m) << 6) + (c4<<2));
        float4 h = (row < 16) ? hA : hB;
        float vx = g4.x + h.x, vy = g4.y + h.y, vz = g4.z + h.z, vw = g4.w + h.w;
        s.x += vx; s.y += vy; s.z += vz; s.w += vw;
        qq.x = fmaf(vx, vx, qq.x); qq.y = fmaf(vy, vy, qq.y);
        qq.z = fmaf(vz, vz, qq.z); qq.w = fmaf(vw, vw, qq.w);
    }
    s.x += __shfl_xor_sync(0xffffffffu, s.x, 16);
    s.y += __shfl_xor_sync(0xffffffffu, s.y, 16);
    s.z += __shfl_xor_sync(0xffffffffu, s.z, 16);
    s.w += __shfl_xor_sync(0xffffffffu, s.w, 16);
    qq.x += __shfl_xor_sync(0xffffffffu, qq.x, 16);
    qq.y += __shfl_xor_sync(0xffffffffu, qq.y, 16);
    qq.z += __shfl_xor_sync(0xffffffffu, qq.z, 16);
    qq.w += __shfl_xor_sync(0xffffffffu, qq.w, 16);
    if (lane < 16) {
        atomicAdd(&bsum[c4*4+0], s.x); atomicAdd(&bsum[c4*4+1], s.y);
        atomicAdd(&bsum[c4*4+2], s.z); atomicAdd(&bsum[c4*4+3], s.w);
        atomicAdd(&bsq[c4*4+0], qq.x); atomicAdd(&bsq[c4*4+1], qq.y);
        atomicAdd(&bsq[c4*4+2], qq.z); atomicAdd(&bsq[c4*4+3], qq.w);
    }
    __syncthreads();
    if (tid < 64) { atomicAdd(&g_sum0[tid], (double)bsum[tid]); atomicAdd(&g_sq0[tid], (double)bsq[tid]); }
}

// ---------------- layer1: persistent, cp.async double-buffered ----------------
__global__ __launch_bounds__(256,2) void layer1_kernel(const float* __restrict__ W1,
                                                       const float* __restrict__ gg0,
                                                       const float* __restrict__ bb0) {
    extern __shared__ float sm[];
    float* Ws   = sm;                    // 4096
    float* xs   = sm + 4096;             // 2*8192
    float* hs   = sm + 4096 + 16384;     // 2*512
    float* s0s  = hs + 1024;             // 64
    float* t0s  = s0s + 64;              // 64
    float* bsum = t0s + 64;              // 64
    float* bsq  = bsum + 64;             // 64
    int*   idxb = (int*)(bsq + 64);      // 2*128
    int tid = threadIdx.x;
    for (int i = tid; i < 4096; i += 256) { int o=i>>6, c=i&63; Ws[swi(o,c)] = W1[i]; }
    if (tid < 64) {
        const double cnt = (double)BB*NN*KK;
        double mean = g_sum0[tid] / cnt;
        double var  = g_sq0[tid] / cnt - mean*mean;
        float sv = gg0[tid] * rsqrtf((float)var + 1e-5f);
        s0s[tid] = sv;
        t0s[tid] = bb0[tid] - (float)mean * sv;
        bsum[tid] = 0.f; bsq[tid] = 0.f;
    }
    int GRID = gridDim.x;
    int T0 = blockIdx.x;
    if (tid < 128) {
        idxb[tid] = g_idx[T0*128 + tid];
        if (T0 + GRID < 4096) idxb[128 + tid] = g_idx[(T0+GRID)*128 + tid];
        cp_async16(shaddr(hs + tid*4), g_H + (size_t)T0*512 + tid*4);
    }
    __syncthreads();
    {
        int bb = T0 >> 9;
#pragma unroll
        for (int k = 0; k < 8; k++) {
            int i = tid + k*256, col = i>>4, c4 = i&15;
            int m = idxb[col];
            cp_async16(shaddr(xs + swi4(col,c4)),
                       g_G + (((size_t)(bb<<12) + m)<<6) + (c4<<2));
        }
    }
    cp_commit();
    int p = 0, t = 0;
    for (int T = T0; T < 4096; T += GRID, t++) {
        int pbase = T*8;
        float* xsp = xs + p*8192;
        float* hsp = hs + p*512;
        cp_wait0(); __syncthreads();
        const float4* s0v = (const float4*)s0s;
        const float4* t0v = (const float4*)t0s;
#pragma unroll
        for (int k = 0; k < 8; k++) {
            int i = tid + k*256, col = i>>4, c4 = i&15;
            float4 g4 = *(float4*)(xsp + swi4(col,c4));
            float4 h4 = *(float4*)(hsp + (col>>4)*64 + (c4<<2));
            float4 sv = s0v[c4], tv = t0v[c4], v;
            v.x = fmaxf(fmaf(sv.x, g4.x+h4.x, tv.x), 0.f);
            v.y = fmaxf(fmaf(sv.y, g4.y+h4.y, tv.y), 0.f);
            v.z = fmaxf(fmaf(sv.z, g4.z+h4.z, tv.z), 0.f);
            v.w = fmaxf(fmaf(sv.w, g4.w+h4.w, tv.w), 0.f);
            *(float4*)(xsp + swi4(col,c4)) = v;
        }
        __syncthreads();
        int Tn = T + GRID;
        int nreg = 0;
        bool hasN2 = false;
        if (Tn < 4096) {
            float* xsn = xs + (p^1)*8192;
            const int* ib = idxb + ((t+1)&1)*128;
            int bb = Tn >> 9;
#pragma unroll
            for (int k = 0; k < 8; k++) {
                int i = tid + k*256, col = i>>4, c4 = i&15;
                int m = ib[col];
                cp_async16(shaddr(xsn + swi4(col,c4)),
                           g_G + (((size_t)(bb<<12) + m)<<6) + (c4<<2));
            }
            if (tid < 128) cp_async16(shaddr(hs + (p^1)*512 + tid*4),
                                      g_H + (size_t)Tn*512 + tid*4);
            cp_commit();
            int T2 = T + 2*GRID;
            if (tid < 128 && T2 < 4096) { nreg = g_idx[T2*128 + tid]; hasN2 = true; }
        }
        int ty = tid >> 5, tx = tid & 31;
        int o0 = ty * 8;
        ull acc2[8][4];
#pragma unroll
        for (int i = 0; i < 8; i++)
#pragma unroll
            for (int j = 0; j < 4; j++) acc2[i][j] = 0ull;
#pragma unroll
        for (int c4 = 0; c4 < 16; c4++) {
            ulonglong2 xv[4];
#pragma unroll
            for (int j = 0; j < 4; j++) xv[j] = *(const ulonglong2*)(xsp + swi4(tx + 32*j, c4));
#pragma unroll
            for (int ih = 0; ih < 2; ih++) {
                ulonglong2 wv[4];
#pragma unroll
                for (int i = 0; i < 4; i++) wv[i] = *(const ulonglong2*)(Ws + swi4(o0 + ih*4 + i, c4));
#pragma unroll
                for (int i = 0; i < 4; i++)
#pragma unroll
                    for (int j = 0; j < 4; j++) {
                        FMA2(acc2[ih*4+i][j], wv[i].x, xv[j].x);
                        FMA2(acc2[ih*4+i][j], wv[i].y, xv[j].y);
                    }
            }
        }
        float v[8][4];
#pragma unroll
        for (int i = 0; i < 8; i++)
#pragma unroll
            for (int j = 0; j < 4; j++) v[i][j] = lo32(acc2[i][j]) + hi32(acc2[i][j]);
#pragma unroll
        for (int j = 0; j < 4; j++) {
            int col = tx + 32*j;
            float* yp = g_y1 + (((size_t)(pbase + (col>>4))*16 + (col&15))<<6) + o0;
            *(float4*)yp       = make_float4(v[0][j], v[1][j], v[2][j], v[3][j]);
            *(float4*)(yp + 4) = make_float4(v[4][j], v[5][j], v[6][j], v[7][j]);
        }
#pragma unroll
        for (int i = 0; i < 8; i++) {
            float ps = 0.f, pq = 0.f;
#pragma unroll
            for (int j = 0; j < 4; j++) { ps += v[i][j]; pq = fmaf(v[i][j], v[i][j], pq); }
#pragma unroll
            for (int s = 16; s >= 1; s >>= 1) {
                ps += __shfl_xor_sync(0xffffffffu, ps, s);
                pq += __shfl_xor_sync(0xffffffffu, pq, s);
            }
            if (tx == 0) { bsum[o0+i] += ps; bsq[o0+i] += pq; }
        }
        if (hasN2) idxb[(t&1)*128 + tid] = nreg;
        __syncthreads();
        p ^= 1;
    }
    if (tid < 64) { atomicAdd(&g_sum1[tid], (double)bsum[tid]); atomicAdd(&g_sq1[tid], (double)bsq[tid]); }
}

// ---------------- layer2: persistent, o-channel-split (2 halves), cp.async double-buffered ----------------
__global__ __launch_bounds__(256,2) void layer2_kernel(const float* __restrict__ W2,
                                                       const float* __restrict__ gg1,
                                                       const float* __restrict__ bb1) {
    extern __shared__ float sm[];
    float* Ws   = sm;                  // 4096 (64 channels x 64)
    float* xs   = sm + 4096;           // 2*8192
    float* s1s  = sm + 4096 + 16384;   // 64
    float* t1s  = s1s + 64;            // 64
    float* bsum = t1s + 64;            // 64
    float* bsq  = bsum + 64;           // 64
    int tid = threadIdx.x;
    int oh = blockIdx.x & 1;           // output-channel half
    int T0 = blockIdx.x >> 1;
    int GRID2 = gridDim.x >> 1;        // 152
    for (int i = tid; i < 4096; i += 256) {
        int o = i>>6, c = i&63;
        Ws[swi(o,c)] = W2[(oh*64 + o)*64 + c];
    }
    if (tid < 64) {
        const double cnt = (double)BB*NN*KK;
        double mean = g_sum1[tid] / cnt;
        double var  = g_sq1[tid] / cnt - mean*mean;
        float sv = gg1[tid] * rsqrtf((float)var + 1e-5f);
        s1s[tid] = sv;
        t1s[tid] = bb1[tid] - (float)mean * sv;
        bsum[tid] = 0.f; bsq[tid] = 0.f;
    }
    __syncthreads();
#pragma unroll
    for (int k = 0; k < 8; k++) {
        int i = tid + k*256, col = i>>4, c4 = i&15;
        cp_async16(shaddr(xs + swi4(col,c4)), g_y1 + (size_t)T0*8192 + col*64 + (c4<<2));
    }
    cp_commit();
    int p = 0;
    for (int T = T0; T < 4096; T += GRID2) {
        int pbase = T*8;
        float* xsp = xs + p*8192;
        cp_wait0(); __syncthreads();
        const float4* s1v = (const float4*)s1s;
        const float4* t1v = (const float4*)t1s;
#pragma unroll
        for (int k = 0; k < 8; k++) {
            int i = tid + k*256, col = i>>4, c4 = i&15;
            float4 y = *(float4*)(xsp + swi4(col,c4));
            float4 sv = s1v[c4], tv = t1v[c4], v;
            v.x = fmaxf(fmaf(sv.x, y.x, tv.x), 0.f);
            v.y = fmaxf(fmaf(sv.y, y.y, tv.y), 0.f);
            v.z = fmaxf(fmaf(sv.z, y.z, tv.z), 0.f);
            v.w = fmaxf(fmaf(sv.w, y.w, tv.w), 0.f);
            *(float4*)(xsp + swi4(col,c4)) = v;
        }
        __syncthreads();
        int Tn = T + GRID2;
        if (Tn < 4096) {
            float* xsn = xs + (p^1)*8192;
#pragma unroll
            for (int k = 0; k < 8; k++) {
                int i = tid + k*256, col = i>>4, c4 = i&15;
                cp_async16(shaddr(xsn + swi4(col,c4)),
                           g_y1 + (size_t)Tn*8192 + col*64 + (c4<<2));
            }
            cp_commit();
        }
        int ty = tid >> 5, tx = tid & 31;
        int o0 = ty * 8;
        ull acc2[8][4];
#pragma unroll
        for (int i = 0; i < 8; i++)
#pragma unroll
            for (int j = 0; j < 4; j++) acc2[i][j] = 0ull;
#pragma unroll
        for (int c4 = 0; c4 < 16; c4++) {
            ulonglong2 xv[4];
#pragma unroll
            for (int j = 0; j < 4; j++) xv[j] = *(const ulonglong2*)(xsp + swi4(tx + 32*j, c4));
#pragma unroll
            for (int ih = 0; ih < 2; ih++) {
                ulonglong2 wv[4];
#pragma unroll
                for (int i = 0; i < 4; i++) wv[i] = *(const ulonglong2*)(Ws + swi4(o0 + ih*4 + i, c4));
#pragma unroll
                for (int i = 0; i < 4; i++)
#pragma unroll
                    for (int j = 0; j < 4; j++) {
                        FMA2(acc2[ih*4+i][j], wv[i].x, xv[j].x);
                        FMA2(acc2[ih*4+i][j], wv[i].y, xv[j].y);
                    }
            }
        }
        float v[8][4];
#pragma unroll
        for (int i = 0; i < 8; i++)
#pragma unroll
            for (int j = 0; j < 4; j++) v[i][j] = lo32(acc2[i][j]) + hi32(acc2[i][j]);
#pragma unroll
        for (int i = 0; i < 8; i++) {
            float ps = 0.f, pq = 0.f;
#pragma unroll
            for (int j = 0; j < 4; j++) { ps += v[i][j]; pq = fmaf(v[i][j], v[i][j], pq); }
#pragma unroll
            for (int s = 16; s >= 1; s >>= 1) {
                ps += __shfl_xor_sync(0xffffffffu, ps, s);
                pq += __shfl_xor_sync(0xffffffffu, pq, s);
            }
            if (tx == 0) { bsum[o0+i] += ps; bsq[o0+i] += pq; }
        }
#pragma unroll
        for (int i = 0; i < 8; i++)
#pragma unroll
            for (int j = 0; j < 4; j++) {
                float mx = v[i][j], mn = v[i][j];
#pragma unroll
                for (int s = 8; s >= 1; s >>= 1) {
                    mx = fmaxf(mx, __shfl_xor_sync(0xffffffffu, mx, s, 16));
                    mn = fminf(mn, __shfl_xor_sync(0xffffffffu, mn, s, 16));
                }
                if ((tx & 15) == 0) {
                    int pp = 2*j + (tx >> 4);
                    g_mx[(size_t)(pbase + pp)*128 + oh*64 + o0 + i] = mx;
                    g_mn[(size_t)(pbase + pp)*128 + oh*64 + o0 + i] = mn;
                }
            }
        __syncthreads();
        p ^= 1;
    }
    if (tid < 64) { atomicAdd(&g_sum2[oh*64 + tid], (double)bsum[tid]); atomicAdd(&g_sq2[oh*64 + tid], (double)bsq[tid]); }
}

__global__ void final_out_kernel(float* __restrict__ out,
                                 const float* __restrict__ gg2,
                                 const float* __restrict__ bb2) {
    __shared__ float tile[32][129];
    __shared__ float s2s[128], t2s[128];
    int tid = threadIdx.x;
    if (tid < 128) {
        const double cnt = (double)BB*NN*KK;
        double mean = g_sum2[tid] / cnt;
        double var  = g_sq2[tid] / cnt - mean*mean;
        float sv = gg2[tid] * rsqrtf((float)var + 1e-5f);
        s2s[tid] = sv;
        t2s[tid] = bb2[tid] - (float)mean * sv;
    }
    __syncthreads();
    int bn0 = blockIdx.x * 32;
    int b = bn0 >> 12, n0 = bn0 & 4095;
    for (int i = tid; i < 32*128; i += 256) {
        int r = i >> 7, o = i & 127;
        float s = s2s[o], t = t2s[o];
        size_t p = (size_t)(bn0 + r)*128 + o;
        float v = fmaxf(fmaf(s, g_mx[p], t), fmaf(s, g_mn[p], t));
        tile[r][o] = fmaxf(v, 0.f);
    }
    __syncthreads();
    for (int i = tid; i < 4096; i += 256) {
        int o = i >> 5, j = i & 31;
        out[(size_t)b*128*NN + o*NN + n0 + j] = tile[j][o];
    }
}

extern "C" void kernel_launch(void* const* d_in, const int* in_sizes, int n_in,
                              void* d_out, int out_size) {
    const float* pos1   = (const float*)d_in[0];
    const float* pos1re = (const float*)d_in[1];
    const float* pos2   = (const float*)d_in[2];
    const float* f1     = (const float*)d_in[3];
    const float* f2     = (const float*)d_in[4];
    const float* W0 = (const float*)d_in[6];
    const float* g0 = (const float*)d_in[7];
    const float* b0 = (const float*)d_in[8];
    const float* W1 = (const float*)d_in[9];
    const float* g1 = (const float*)d_in[10];
    const float* b1 = (const float*)d_in[11];
    const float* W2 = (const float*)d_in[12];
    const float* g2 = (const float*)d_in[13];
    const float* b2 = (const float*)d_in[14];

    float* out = (float*)d_out;
    const size_t featElems = (size_t)BB*128*NN;
    const size_t posElems  = (size_t)BB*3*NN;
    float* featOut = out + ((size_t)out_size - featElems);
    if ((size_t)out_size > featElems)
        cudaMemcpyAsync(out, pos1, posElems*sizeof(float), cudaMemcpyDeviceToDevice);

    static bool attrs_set = false;
    if (!attrs_set) {
        cudaFuncSetAttribute(layer1_kernel, cudaFuncAttributeMaxDynamicSharedMemorySize, 88064);
        cudaFuncSetAttribute(layer2_kernel, cudaFuncAttributeMaxDynamicSharedMemorySize, 83200);
        attrs_set = true;
    }

    knn_part_kernel<<<dim3(32, 8, 2), 128>>>(pos1re, pos2);
    merge_gh_kernel<<<640, 256>>>(pos1, pos2, f1, f2, W0);
    stats0_kernel<<<2048, 256>>>();
    layer1_kernel<<<304, 256, 88064>>>(W1, g0, b0);
    layer2_kernel<<<304, 256, 83200>>>(W2, g1, b1);
    final_out_kernel<<<1024, 256>>>(featOut, g2, b2);
}